// round 17
// baseline (speedup 1.0000x reference)
#include <cuda_runtime.h>
#include <cstdint>

#define NN 16
#define NSTEP 17
#define BMAX 131072
#define NT 256
#define MAXSLOT 12

// thread-private fragment-ordered activation slots + fragment-packed split weights
__device__ float g_slot[MAXSLOT][BMAX * 64];
__device__ uint4 g_wt[NSTEP][1024];      // [(kk*8+nt)*32+lane] = {bh0,bh1,bl0,bl1}

struct Plan {
    int nslot;
    int usePrev[NSTEP];      // 1: prev step's output (registers) is a source addend
    int nLoad[NSTEP];        // number of slot loads
    unsigned char loadSlot[NSTEP][NN];
    int outSlot[NSTEP];      // >=0: store to slot; -1: sink (agg); -2: reg-only
    int act[NSTEP];
};

// ---------------- helpers ----------------

__device__ __forceinline__ float uf(uint32_t u) { return __uint_as_float(u); }
__device__ __forceinline__ uint32_t bf2(float lo, float hi) {  // pack: low16=lo
    uint32_t r;
    asm("cvt.rn.bf16x2.f32 %0, %1, %2;" : "=r"(r) : "f"(hi), "f"(lo));
    return r;
}
__device__ __forceinline__ float lo16(uint32_t h) { return uf(h << 16); }
__device__ __forceinline__ float hi16(uint32_t h) { return uf(h & 0xFFFF0000u); }

__device__ __forceinline__ void mma_bf16(float* c, uint32_t a0, uint32_t a1,
                                         uint32_t a2, uint32_t a3,
                                         uint32_t b0, uint32_t b1) {
    asm volatile(
        "mma.sync.aligned.m16n8k16.row.col.f32.bf16.bf16.f32 "
        "{%0,%1,%2,%3}, {%4,%5,%6,%7}, {%8,%9}, {%0,%1,%2,%3};"
        : "+f"(c[0]), "+f"(c[1]), "+f"(c[2]), "+f"(c[3])
        : "r"(a0), "r"(a1), "r"(a2), "r"(a3), "r"(b0), "r"(b1));
}

__device__ __forceinline__ float fast_tanh(float x) {
    float e = __expf(2.f * x);
    return 1.f - __fdividef(2.f, e + 1.f);
}
// GRAPH_ACTS = [tanh, elu, softplus, sin, gaussian]
__device__ __forceinline__ float actf(int id, float v) {
    switch (id) {
        case 0:  return fast_tanh(v);
        case 1:  return v > 0.f ? v : (__expf(v) - 1.f);
        case 2:  return fmaxf(v, 0.f) + __logf(1.f + __expf(-fabsf(v)));
        case 3:  return __sinf(v);
        default: return __expf(-0.5f * v * v);
    }
}

// ---------------- weight fragment kernel ----------------
// B col-major n8k16 fragment: b0 = {B[k0][n], B[k0+1][n]}, b1 = {B[k0+8][n], B[k0+9][n]}
// with n = nt*8 + (lane>>2), k0 = kk*16 + (lane&3)*2;  B[k][n] = W[n][k]

__global__ void wt_kernel(const float* __restrict__ W1, const float* __restrict__ gW) {
    int l = blockIdx.x;
    const float* src = (l == 0) ? W1 : gW + (l - 1) * 4096;
    for (int e = threadIdx.x; e < 1024; e += blockDim.x) {
        int lane = e & 31, nt = (e >> 5) & 7, kk = e >> 8;
        int g = lane >> 2, tid = lane & 3;
        int n = nt * 8 + g;
        int k0 = kk * 16 + tid * 2;
        float w00 = src[n * 64 + k0],     w01 = src[n * 64 + k0 + 1];
        float w10 = src[n * 64 + k0 + 8], w11 = src[n * 64 + k0 + 9];
        uint32_t h0 = bf2(w00, w01), h1 = bf2(w10, w11);
        uint32_t l0 = bf2(w00 - lo16(h0), w01 - hi16(h0));
        uint32_t l1 = bf2(w10 - lo16(h1), w11 - hi16(h1));
        g_wt[l][e] = make_uint4(h0, h1, l0, l1);
    }
}

// ---------------- main kernel (no smem, no barriers) ----------------

__global__ void __launch_bounds__(NT, 2)
inr_kernel(const float* __restrict__ inp, const float* __restrict__ lats,
           const float* __restrict__ Wl, const float* __restrict__ bl,
           const float* __restrict__ Wx, const float* __restrict__ Wy,
           const float* __restrict__ Wr, const float* __restrict__ b1,
           const float* __restrict__ gB, const float* __restrict__ outW,
           const float* __restrict__ outb, const float* __restrict__ scale,
           float* __restrict__ out, Plan pl) {
    const int t    = threadIdx.x;
    const int w    = t >> 5, lane = t & 31;
    const int g    = lane >> 2, tid = lane & 3;
    const int blk  = blockIdx.x;
    const int sA   = blk * 128 + w * 16 + g;      // fragment rows: sA, sA+8
    const int sB   = sA + 8;
    const int fragBase = blk * 8192 + (w * 8) * 128 + lane * 4;  // float offset (nt=0)

    float cur[32];   // previous step's output / current source, frag order [nt*4+c]

    // ---- encode -> cur (registers; never stored) ----
    {
        float xA = inp[sA*3+0], yA = inp[sA*3+1], rA = inp[sA*3+2];
        float xB = inp[sB*3+0], yB = inp[sB*3+1], rB = inp[sB*3+2];
        const float4* lpA = (const float4*)(lats + sA * 8);
        const float4* lpB = (const float4*)(lats + sB * 8);
        float4 lA0 = lpA[0], lA1 = lpA[1];
        float4 lB0 = lpB[0], lB1 = lpB[1];
#pragma unroll
        for (int nt = 0; nt < 8; nt++) {
#pragma unroll
            for (int c = 0; c < 2; c++) {
                int o = nt * 8 + tid * 2 + c;
                const float4* wlr = (const float4*)(Wl + o * 8);
                float4 w0 = wlr[0], w1 = wlr[1];
                float blo = __ldg(bl + o), wx = __ldg(Wx + o);
                float wy = __ldg(Wy + o), wr = __ldg(Wr + o);
                float preA = blo, preB = blo;
                preA = fmaf(lA0.x,w0.x,preA); preA = fmaf(lA0.y,w0.y,preA);
                preA = fmaf(lA0.z,w0.z,preA); preA = fmaf(lA0.w,w0.w,preA);
                preA = fmaf(lA1.x,w1.x,preA); preA = fmaf(lA1.y,w1.y,preA);
                preA = fmaf(lA1.z,w1.z,preA); preA = fmaf(lA1.w,w1.w,preA);
                preB = fmaf(lB0.x,w0.x,preB); preB = fmaf(lB0.y,w0.y,preB);
                preB = fmaf(lB0.z,w0.z,preB); preB = fmaf(lB0.w,w0.w,preB);
                preB = fmaf(lB1.x,w1.x,preB); preB = fmaf(lB1.y,w1.y,preB);
                preB = fmaf(lB1.z,w1.z,preB); preB = fmaf(lB1.w,w1.w,preB);
                float lvA = fast_tanh(preA), lvB = fast_tanh(preB);
                float xvA = fast_tanh(xA * wx), xvB = fast_tanh(xB * wx);
                float yvA, yvB, rvA, rvB;
                { float z = yA * wy; yvA = fmaxf(z,0.f) + __logf(1.f + __expf(-fabsf(z))); }
                { float z = yB * wy; yvB = fmaxf(z,0.f) + __logf(1.f + __expf(-fabsf(z))); }
                { float z = rA * wr; rvA = z > 0.f ? z : (__expf(z) - 1.f); }
                { float z = rB * wr; rvB = z > 0.f ? z : (__expf(z) - 1.f); }
                float uA = xvA + yvA + rvA + lvA;
                float uB = xvB + yvB + rvB + lvB;
                cur[nt*4 + c]     = __expf(-0.5f * uA * uA);
                cur[nt*4 + 2 + c] = __expf(-0.5f * uB * uB);
            }
        }
    }

    float agg[32];
#pragma unroll
    for (int i = 0; i < 32; i++) agg[i] = 0.f;

    // ---- 17 layers, fully warp-local ----
    for (int st = 0; st < NSTEP; st++) {
        // ---- gather source into cur ----
        int nl = pl.nLoad[st];
        if (nl > 0) {
            int first = pl.usePrev[st] ? 0 : 1;
            if (!pl.usePrev[st]) {
                const float* pp = g_slot[pl.loadSlot[st][0]] + fragBase;
#pragma unroll
                for (int nt = 0; nt < 8; nt++) {
                    float4 v = *(const float4*)(pp + nt * 128);
                    cur[nt*4+0] = v.x; cur[nt*4+1] = v.y;
                    cur[nt*4+2] = v.z; cur[nt*4+3] = v.w;
                }
            }
            for (int p = first; p < nl; p++) {
                const float* pp = g_slot[pl.loadSlot[st][p]] + fragBase;
#pragma unroll
                for (int nt = 0; nt < 8; nt++) {
                    float4 v = *(const float4*)(pp + nt * 128);
                    cur[nt*4+0] += v.x; cur[nt*4+1] += v.y;
                    cur[nt*4+2] += v.z; cur[nt*4+3] += v.w;
                }
            }
        }
        // (usePrev && nl==0): cur already holds the source

        // split fp32 -> bf16 hi/lo A-fragments
        uint32_t Ah[16], Al[16];
#pragma unroll
        for (int nt = 0; nt < 8; nt++) {
            float a0 = cur[nt*4+0], a1 = cur[nt*4+1];
            uint32_t h0 = bf2(a0, a1);
            Ah[nt*2]   = h0;
            Al[nt*2]   = bf2(a0 - lo16(h0), a1 - hi16(h0));
            float a2 = cur[nt*4+2], a3 = cur[nt*4+3];
            uint32_t h1 = bf2(a2, a3);
            Ah[nt*2+1] = h1;
            Al[nt*2+1] = bf2(a2 - lo16(h1), a3 - hi16(h1));
        }

        float acc[8][4];
#pragma unroll
        for (int nt = 0; nt < 8; nt++)
#pragma unroll
            for (int c = 0; c < 4; c++) acc[nt][c] = 0.f;

        const uint4* wt = g_wt[st] + lane;
#pragma unroll
        for (int kk = 0; kk < 4; kk++) {
            uint32_t a0h = Ah[4*kk],   a1h = Ah[4*kk+1];
            uint32_t a2h = Ah[4*kk+2], a3h = Ah[4*kk+3];
            uint32_t a0l = Al[4*kk],   a1l = Al[4*kk+1];
            uint32_t a2l = Al[4*kk+2], a3l = Al[4*kk+3];
#pragma unroll
            for (int nt = 0; nt < 8; nt++) {
                uint4 b = __ldg(wt + (kk * 8 + nt) * 32);
                mma_bf16(acc[nt], a0h, a1h, a2h, a3h, b.x, b.y);   // Ah*Bh
                mma_bf16(acc[nt], a0h, a1h, a2h, a3h, b.z, b.w);   // Ah*Bl
                mma_bf16(acc[nt], a0l, a1l, a2l, a3l, b.x, b.y);   // Al*Bh
            }
        }

        // epilogue: bias + act -> cur; optional store / sink aggregation
        const float* bias = (st == 0) ? b1 : gB + (st - 1) * 64;
        int aid = pl.act[st];
        int os  = pl.outSlot[st];
        float* ob = g_slot[(os >= 0) ? os : 0] + fragBase;
#pragma unroll
        for (int nt = 0; nt < 8; nt++) {
            float b0  = __ldg(bias + nt * 8 + tid * 2);
            float b1v = __ldg(bias + nt * 8 + tid * 2 + 1);
            float v0 = actf(aid, acc[nt][0] + b0);
            float v1 = actf(aid, acc[nt][1] + b1v);
            float v2 = actf(aid, acc[nt][2] + b0);
            float v3 = actf(aid, acc[nt][3] + b1v);
            cur[nt*4+0] = v0; cur[nt*4+1] = v1;
            cur[nt*4+2] = v2; cur[nt*4+3] = v3;
            if (os >= 0) {
                *(float4*)(ob + nt * 128) = make_float4(v0, v1, v2, v3);
            } else if (os == -1) {
                agg[nt*4+0] += v0; agg[nt*4+1] += v1;
                agg[nt*4+2] += v2; agg[nt*4+3] += v3;
            }
        }
    }

    // ---- head: sigmoid((agg @ outW.T + outb) * scale) ----
    float sc = __ldg(scale);
#pragma unroll
    for (int ch = 0; ch < 3; ch++) {
        float pA = 0.f, pB = 0.f;
#pragma unroll
        for (int nt = 0; nt < 8; nt++) {
            int o = nt * 8 + tid * 2;
            float w0v = __ldg(outW + ch * 64 + o);
            float w1v = __ldg(outW + ch * 64 + o + 1);
            pA = fmaf(agg[nt*4+0], w0v, pA); pA = fmaf(agg[nt*4+1], w1v, pA);
            pB = fmaf(agg[nt*4+2], w0v, pB); pB = fmaf(agg[nt*4+3], w1v, pB);
        }
        pA += __shfl_xor_sync(0xFFFFFFFFu, pA, 1);
        pA += __shfl_xor_sync(0xFFFFFFFFu, pA, 2);
        pB += __shfl_xor_sync(0xFFFFFFFFu, pB, 1);
        pB += __shfl_xor_sync(0xFFFFFFFFu, pB, 2);
        if (tid == 0) {
            float ob_ = __ldg(outb + ch);
            float rA = (pA + ob_) * sc;
            float rB = (pB + ob_) * sc;
            out[sA * 3 + ch] = __fdividef(1.f, 1.f + __expf(-rA));
            out[sB * 3 + ch] = __fdividef(1.f, 1.f + __expf(-rB));
        }
    }
}

// ---------------- host: graph replication + pass-through slot plan ----------------

namespace {

struct MT19937 {
    uint32_t mt[624];
    int mti;
    void seed(uint32_t sd) {
        mt[0] = sd;
        for (int i = 1; i < 624; i++)
            mt[i] = 1812433253u * (mt[i-1] ^ (mt[i-1] >> 30)) + (uint32_t)i;
        mti = 624;
    }
    uint32_t next32() {
        if (mti >= 624) {
            for (int i = 0; i < 624; i++) {
                uint32_t y = (mt[i] & 0x80000000u) | (mt[(i+1)%624] & 0x7fffffffu);
                uint32_t v = mt[(i+397)%624] ^ (y >> 1);
                if (y & 1u) v ^= 0x9908b0dfu;
                mt[i] = v;
            }
            mti = 0;
        }
        uint32_t y = mt[mti++];
        y ^= y >> 11; y ^= (y << 7) & 0x9d2c5680u;
        y ^= (y << 15) & 0xefc60000u; y ^= y >> 18;
        return y;
    }
    double rnd() {
        uint32_t a = next32() >> 5, b = next32() >> 6;
        return (a * 67108864.0 + b) / 9007199254740992.0;
    }
    uint32_t randint(uint32_t n) {
        uint32_t rng = n - 1;
        if (rng == 0) return 0;
        uint32_t mask = rng;
        mask |= mask >> 1; mask |= mask >> 2; mask |= mask >> 4;
        mask |= mask >> 8; mask |= mask >> 16;
        uint32_t v;
        do { v = next32() & mask; } while (v > rng);
        return v;
    }
};

void build_plan(Plan& P) {
    MT19937 rng; rng.seed(0u);
    const int n = NN;
    bool adj[NN][NN] = {};
    for (int i = 0; i < n; i++)
        for (int d = 1; d <= 2; d++) {
            int j = (i + d) % n;
            if (rng.rnd() < 0.75) j = (int)rng.randint((uint32_t)n);
            int a = i < j ? i : j, b = i < j ? j : i;
            if (a != b) adj[a][b] = true;
        }
    unsigned pm[NN] = {};
    for (int a = 0; a < n; a++)
        for (int b = 0; b < n; b++)
            if (adj[a][b]) pm[b] |= 1u << a;
    for (int j = 1; j < n; j++)
        if (!pm[j]) {
            uint32_t a = rng.randint((uint32_t)j);
            adj[a][j] = true;
            pm[j] |= 1u << a;
        }
    bool isSink[NN];
    for (int j = 0; j < n; j++) {
        bool hs = false;
        for (int b = 0; b < n; b++) if (adj[j][b]) hs = true;
        isSink[j] = !hs;
    }

    // values: 0..15 = nodes, 16 = f. producer step: f->0, node j->j+1.
    // predecessors per step (bitmask over values):
    unsigned predv[NSTEP];
    predv[0] = 0;                                  // enc lives in registers
    for (int j = 0; j < n; j++)
        predv[j + 1] = pm[j] ? pm[j] : (1u << 16);

    int prodStep[17];
    prodStep[16] = 0;
    for (int j = 0; j < n; j++) prodStep[j] = j + 1;

    // slot-consumers: consumers at step != prodStep+1 must read from a slot
    int lastSlotUse[17];
    bool needSlot[17];
    for (int v = 0; v < 17; v++) { lastSlotUse[v] = -1; needSlot[v] = false; }
    for (int st = 1; st < NSTEP; st++)
        for (int v = 0; v < 17; v++)
            if ((predv[st] >> v) & 1)
                if (st != prodStep[v] + 1) {
                    needSlot[v] = true;
                    if (st > lastSlotUse[v]) lastSlotUse[v] = st;
                }

    int slotOf[17];
    for (int v = 0; v < 17; v++) slotOf[v] = -1;
    int freeS[24], nFree = 0, ns = 0;
    auto alloc = [&]() { return nFree ? freeS[--nFree] : ns++; };

    for (int st = 0; st < NSTEP; st++) {
        int prevVal = (st == 0) ? -1 : ((st - 1 == 0) ? 16 : st - 2);
        // sources
        P.usePrev[st] = (st == 0) ? 1 : 0;
        P.nLoad[st] = 0;
        for (int v = 0; v < 17; v++)
            if ((predv[st] >> v) & 1) {
                if (v == prevVal) P.usePrev[st] = 1;
                else P.loadSlot[st][P.nLoad[st]++] = (unsigned char)slotOf[v];
            }
        P.act[st] = (st == 0) ? 3 : (st - 1) % 5;

        // release slots whose last slot-read is this step (reads precede writes
        // in per-thread program order, so reuse for this step's output is safe)
        for (int v = 0; v < 17; v++)
            if (needSlot[v] && lastSlotUse[v] == st && slotOf[v] >= 0) {
                freeS[nFree++] = slotOf[v];
                slotOf[v] = -1;
            }

        // output
        int pv = (st == 0) ? 16 : st - 1;
        if (st > 0 && isSink[st - 1]) {
            P.outSlot[st] = -1;                    // register aggregation
        } else if (needSlot[pv]) {
            slotOf[pv] = alloc();
            P.outSlot[st] = slotOf[pv];
        } else {
            P.outSlot[st] = -2;                    // consumed only via registers
        }
    }
    P.nslot = ns;
}

}  // namespace

// ---------------- launch ----------------

extern "C" void kernel_launch(void* const* d_in, const int* in_sizes, int n_in,
                              void* d_out, int out_size) {
    (void)n_in; (void)out_size;
    Plan pl;
    build_plan(pl);

    const int B = in_sizes[0] / 3;
    const int ntiles = B / 128;

    // stage split-bf16 fragment-packed weights for W1 + 16 graph nodes
    wt_kernel<<<NSTEP, 256>>>((const float*)d_in[7], (const float*)d_in[9]);

    inr_kernel<<<ntiles, NT>>>(
        (const float*)d_in[0],  (const float*)d_in[1],  (const float*)d_in[2],
        (const float*)d_in[3],  (const float*)d_in[4],  (const float*)d_in[5],
        (const float*)d_in[6],  (const float*)d_in[8],  (const float*)d_in[10],
        (const float*)d_in[11], (const float*)d_in[12], (const float*)d_in[13],
        (float*)d_out, pl);
}